// round 5
// baseline (speedup 1.0000x reference)
#include <cuda_runtime.h>
#include <cstdint>

#define DEVINL __device__ __forceinline__

constexpr int BB = 256;            // batch
constexpr int II = 512;            // input dim
constexpr int RR = 1024;           // hidden dim
constexpr int UU = 11;             // unroll length
constexpr int NSTEP = 10;          // steps that matter (step 10 is dead)
constexpr int OUTLD = UU * RR;     // output row stride
constexpr int PRELD = NSTEP * 4 * RR;  // PreX row stride

constexpr int BM  = 64;            // CTA m-tile
constexpr int KC  = 32;            // k-chunk
constexpr int ALD = KC + 4;        // padded smem row (36) -> conflict-free frags
constexpr int NST = 3;             // pipeline stages

// Scratch (allocation-free rule: __device__ globals)
__device__ __align__(16) float g_preX[(size_t)BB * PRELD];
__device__ __align__(16) float g_h0buf[2][BB * RR];
__device__ __align__(16) float g_c0[BB * RR];
__device__ __align__(16) float g_c1[BB * RR];

struct Smem {
    float As[NST][BM][ALD];
    float Bs[NST][128][ALD];
};
constexpr size_t SMEM_BYTES = sizeof(Smem);   // 3*(64+128)*36*4 = 82,944 B

DEVINL void cp16(float* s, const float* g) {
    uint32_t sa = (uint32_t)__cvta_generic_to_shared(s);
    asm volatile("cp.async.cg.shared.global [%0], [%1], 16;" :: "r"(sa), "l"(g));
}
DEVINL void cp_commit() { asm volatile("cp.async.commit_group;"); }
DEVINL void cp_wait0()  { asm volatile("cp.async.wait_group 0;"); }
DEVINL void cp_wait1()  { asm volatile("cp.async.wait_group 1;"); }

DEVINL uint32_t f2tf(float f) {
    uint32_t u; asm("cvt.rna.tf32.f32 %0, %1;" : "=r"(u) : "f"(f)); return u;
}

DEVINL void mma8(float* d, const uint32_t* a, const uint32_t* b) {
    asm volatile(
        "mma.sync.aligned.m16n8k8.row.col.f32.tf32.tf32.f32 "
        "{%0,%1,%2,%3}, {%4,%5,%6,%7}, {%8,%9}, {%0,%1,%2,%3};"
        : "+f"(d[0]), "+f"(d[1]), "+f"(d[2]), "+f"(d[3])
        : "r"(a[0]), "r"(a[1]), "r"(a[2]), "r"(a[3]), "r"(b[0]), "r"(b[1]));
}

DEVINL float sigm(float x) { return 1.0f / (1.0f + expf(-x)); }

// Unified TN GEMM body, 128 threads (2x2 warps of 32m x 64n), CTA tile 64x128.
// The 128 output columns are 4 groups of 32 with W-row stride `gstride` (gates).
//   EPI 0: precompute -> acc + e0[col] + e1[col] into hout (PreX)
//   EPI 1: layer0 cell -> base = PreX (e0), state c0, write h0_next
//   EPI 2: layer1 cell -> base = bi1+bh1, state c1, write h1
template<int EPI, int NPAIRS>
DEVINL void gemm_body(Smem& sm, int m0, int nbase,
                      const float* __restrict__ A0, int lda0,
                      const float* __restrict__ W0,
                      const float* __restrict__ A1, int lda1,
                      const float* __restrict__ W1,
                      int K, int gstride,
                      const float* __restrict__ e0,
                      const float* __restrict__ e1,
                      float* __restrict__ cst,
                      float* __restrict__ hout, int ldh)
{
    const int tid  = threadIdx.x;
    const int warp = tid >> 5, lane = tid & 31;
    const int wm = warp >> 1, wn = warp & 1;       // 2x2 warps
    const int gid = lane >> 2, tig = lane & 3;

    // loader geometry: 128 threads cover 16 rows x 32 cols (128B rows of KC=32)
    const int r0 = tid >> 3;                 // 0..15
    const int c0 = (tid & 7) << 2;           // 0,4,...,28

    // per-pair global pointers at (row r0, col c0)
    const float* Ag[NPAIRS];
    const float* Wg[NPAIRS][8];
    #pragma unroll
    for (int p = 0; p < NPAIRS; p++) {
        const float* A   = (p == 0) ? A0 : A1;
        const int    lda = (p == 0) ? lda0 : lda1;
        const float* W   = (p == 0) ? W0 : W1;
        Ag[p] = A + (size_t)(m0 + r0) * lda + c0;
        #pragma unroll
        for (int i = 0; i < 8; i++) {
            const int grow = nbase + (i >> 1) * gstride + r0 + (i & 1) * 16;
            Wg[p][i] = W + (size_t)grow * K + c0;
        }
    }
    const int ldaP[2] = { lda0, lda1 };

    const int nk = K / KC;
    const int T  = NPAIRS * nk;

    float acc[2][4][2][4];
    #pragma unroll
    for (int a = 0; a < 2; a++)
        #pragma unroll
        for (int g = 0; g < 4; g++)
            #pragma unroll
            for (int f = 0; f < 2; f++)
                #pragma unroll
                for (int c = 0; c < 4; c++) acc[a][g][f][c] = 0.0f;

    // --- prologue: chunks 0,1 ---
    #pragma unroll 1
    for (int ci = 0; ci < 2 && ci < T; ci++) {
        const int buf  = ci % NST;
        const int p    = (NPAIRS == 2 && ci >= nk) ? 1 : 0;
        const int koff = (p ? ci - nk : ci) * KC;
        #pragma unroll
        for (int i = 0; i < 4; i++)
            cp16(&sm.As[buf][r0 + 16 * i][c0], Ag[p] + koff + (size_t)16 * i * ldaP[p]);
        #pragma unroll
        for (int i = 0; i < 8; i++)
            cp16(&sm.Bs[buf][r0 + 16 * i][c0], Wg[p][i] + koff);
        cp_commit();
    }

    #pragma unroll 1
    for (int t = 0; t < T; t++) {
        if (t + 1 < T) cp_wait1(); else cp_wait0();
        __syncthreads();

        const int ci2 = t + 2;
        if (ci2 < T) {
            const int buf  = ci2 % NST;
            const int p    = (NPAIRS == 2 && ci2 >= nk) ? 1 : 0;
            const int koff = (p ? ci2 - nk : ci2) * KC;
            #pragma unroll
            for (int i = 0; i < 4; i++)
                cp16(&sm.As[buf][r0 + 16 * i][c0], Ag[p] + koff + (size_t)16 * i * ldaP[p]);
            #pragma unroll
            for (int i = 0; i < 8; i++)
                cp16(&sm.Bs[buf][r0 + 16 * i][c0], Wg[p][i] + koff);
            cp_commit();
        }

        const int buf = t % NST;
        #pragma unroll
        for (int ks = 0; ks < KC / 8; ks++) {
            const int ko = ks * 8;
            uint32_t ua[2][4];
            #pragma unroll
            for (int mi = 0; mi < 2; mi++) {
                const float* ab = &sm.As[buf][wm * 32 + mi * 16 + gid][ko + tig];
                ua[mi][0] = f2tf(ab[0]);
                ua[mi][1] = f2tf(ab[8 * ALD]);
                ua[mi][2] = f2tf(ab[4]);
                ua[mi][3] = f2tf(ab[8 * ALD + 4]);
            }
            uint32_t ub[4][2][2];
            #pragma unroll
            for (int g = 0; g < 4; g++)
                #pragma unroll
                for (int f = 0; f < 2; f++) {
                    const float* bb = &sm.Bs[buf][g * 32 + wn * 16 + f * 8 + gid][ko + tig];
                    ub[g][f][0] = f2tf(bb[0]);
                    ub[g][f][1] = f2tf(bb[4]);
                }
            #pragma unroll
            for (int mi = 0; mi < 2; mi++)
                #pragma unroll
                for (int g = 0; g < 4; g++)
                    #pragma unroll
                    for (int f = 0; f < 2; f++)
                        mma8(acc[mi][g][f], ua[mi], ub[g][f]);
        }
    }

    // ---- epilogue ----
    #pragma unroll
    for (int mi = 0; mi < 2; mi++) {
        #pragma unroll
        for (int half = 0; half < 2; half++) {
            const int row = wm * 32 + mi * 16 + gid + half * 8;
            const int b = m0 + row;
            #pragma unroll
            for (int cc = 0; cc < 2; cc++) {
                const int reg = half * 2 + cc;
                if constexpr (EPI == 0) {
                    #pragma unroll
                    for (int g = 0; g < 4; g++)
                        #pragma unroll
                        for (int f = 0; f < 2; f++) {
                            const int col = nbase + g * gstride + wn * 16 + f * 8 + 2 * tig + cc;
                            hout[(size_t)b * ldh + col] = acc[mi][g][f][reg] + e0[col] + e1[col];
                        }
                } else {
                    #pragma unroll
                    for (int f = 0; f < 2; f++) {
                        const int r = nbase + wn * 16 + f * 8 + 2 * tig + cc;
                        float pre[4];
                        #pragma unroll
                        for (int g = 0; g < 4; g++) {
                            float base;
                            if constexpr (EPI == 1)
                                base = e0[(size_t)b * PRELD + g * RR + r];
                            else
                                base = e0[g * RR + r] + e1[g * RR + r];
                            pre[g] = acc[mi][g][f][reg] + base;
                        }
                        const float cprev = cst[b * RR + r];
                        const float iv = sigm(pre[0]);
                        const float fv = sigm(pre[1]);
                        const float ov = sigm(pre[2]);
                        const float gv = tanhf(pre[3]);
                        const float cnew = fv * cprev + iv * gv;
                        const float hnew = ov * tanhf(cnew);
                        cst[b * RR + r] = cnew;
                        hout[(size_t)b * ldh + r] = hnew;
                    }
                }
            }
        }
    }
}

// ---- kernels ----

__global__ __launch_bounds__(128, 4)
void k_pre(const float* __restrict__ x, const float* __restrict__ Wi0,
           const float* __restrict__ bi0, const float* __restrict__ bh0,
           float* __restrict__ preX)
{
    extern __shared__ float smraw[];
    Smem& sm = *reinterpret_cast<Smem*>(smraw);
    gemm_body<0, 1>(sm, blockIdx.x * BM, blockIdx.y * 128,
                    x, II, Wi0, nullptr, 0, nullptr,
                    II, 32, bi0, bh0, nullptr, preX, PRELD);
}

__global__ __launch_bounds__(128, 4)
void k_l0(const float* __restrict__ h0cur, const float* __restrict__ Wh0u,
          const float* __restrict__ preXu, float* __restrict__ c0,
          float* __restrict__ h0nxt)
{
    extern __shared__ float smraw[];
    Smem& sm = *reinterpret_cast<Smem*>(smraw);
    gemm_body<1, 1>(sm, blockIdx.x * BM, blockIdx.y * 32,
                    h0cur, RR, Wh0u, nullptr, 0, nullptr,
                    RR, RR, preXu, nullptr, c0, h0nxt, RR);
}

__global__ __launch_bounds__(128, 4)
void k_l1(const float* __restrict__ h0cur, const float* __restrict__ Wi1u,
          const float* __restrict__ h1in, const float* __restrict__ Wh1u,
          const float* __restrict__ bi1u, const float* __restrict__ bh1u,
          float* __restrict__ c1, float* __restrict__ h1out)
{
    extern __shared__ float smraw[];
    Smem& sm = *reinterpret_cast<Smem*>(smraw);
    gemm_body<2, 2>(sm, blockIdx.x * BM, blockIdx.y * 32,
                    h0cur, RR, Wi1u, h1in, OUTLD, Wh1u,
                    RR, RR, bi1u, bh1u, c1, h1out, OUTLD);
}

// Combined step: L1(u) [y even] and L0(u+1) [y odd] are independent (both
// consume h0 from L0(u)). Even/odd mapping pairs long (K=2048) and short
// (K=1024) CTAs across SMs for balanced residency.
__global__ __launch_bounds__(128, 4)
void k_step(const float* __restrict__ h0cur, float* __restrict__ h0nxt,
            const float* __restrict__ Wi1u, const float* __restrict__ Wh1u,
            const float* __restrict__ bi1u, const float* __restrict__ bh1u,
            const float* __restrict__ h1in, float* __restrict__ h1out,
            const float* __restrict__ Wh0n, const float* __restrict__ preXn,
            float* __restrict__ c0, float* __restrict__ c1)
{
    extern __shared__ float smraw[];
    Smem& sm = *reinterpret_cast<Smem*>(smraw);
    const int m0 = blockIdx.x * BM;
    const int y  = blockIdx.y;
    if ((y & 1) == 0) {
        gemm_body<2, 2>(sm, m0, (y >> 1) * 32,
                        h0cur, RR, Wi1u, h1in, OUTLD, Wh1u,
                        RR, RR, bi1u, bh1u, c1, h1out, OUTLD);
    } else {
        gemm_body<1, 1>(sm, m0, (y >> 1) * 32,
                        h0cur, RR, Wh0n, nullptr, 0, nullptr,
                        RR, RR, preXn, nullptr, c0, h0nxt, RR);
    }
}

__global__ void init_states(const float* __restrict__ st, float* __restrict__ out) {
    int idx = blockIdx.x * blockDim.x + threadIdx.x;
    if (idx >= BB * RR) return;
    int b = idx >> 10, r = idx & (RR - 1);
    const float* s = st + (size_t)b * (4 * RR);
    g_h0buf[0][idx] = s[r];                        // h0
    g_c0[idx]       = s[RR + r];                   // c0
    out[(size_t)b * OUTLD + r] = s[2 * RR + r];    // h1 -> output col 0 (state)
    g_c1[idx]       = s[3 * RR + r];               // c1
}

extern "C" void kernel_launch(void* const* d_in, const int* in_sizes, int n_in,
                              void* d_out, int out_size)
{
    const float* x   = (const float*)d_in[0];
    const float* ini = (const float*)d_in[1];
    const float* Wi0 = (const float*)d_in[2];
    const float* bi0 = (const float*)d_in[3];
    const float* Wh0 = (const float*)d_in[4];
    const float* bh0 = (const float*)d_in[5];
    const float* Wi1 = (const float*)d_in[6];
    const float* bi1 = (const float*)d_in[7];
    const float* Wh1 = (const float*)d_in[8];
    const float* bh1 = (const float*)d_in[9];
    float* out = (float*)d_out;

    static bool attr_done = false;
    if (!attr_done) {
        cudaFuncSetAttribute(k_pre,  cudaFuncAttributeMaxDynamicSharedMemorySize, (int)SMEM_BYTES);
        cudaFuncSetAttribute(k_l0,   cudaFuncAttributeMaxDynamicSharedMemorySize, (int)SMEM_BYTES);
        cudaFuncSetAttribute(k_l1,   cudaFuncAttributeMaxDynamicSharedMemorySize, (int)SMEM_BYTES);
        cudaFuncSetAttribute(k_step, cudaFuncAttributeMaxDynamicSharedMemorySize, (int)SMEM_BYTES);
        attr_done = true;
    }

    float *preX, *h0buf, *c0, *c1;
    cudaGetSymbolAddress((void**)&preX,  g_preX);
    cudaGetSymbolAddress((void**)&h0buf, g_h0buf);
    cudaGetSymbolAddress((void**)&c0,    g_c0);
    cudaGetSymbolAddress((void**)&c1,    g_c1);

    auto h0b = [&](int i) { return h0buf + (size_t)i * BB * RR; };

    init_states<<<(BB * RR) / 256, 256>>>(ini, out);

    // PreX = x @ Wi0[0:10].T + bi0 + bh0
    k_pre<<<dim3(BB / BM, PRELD / 128), 128, SMEM_BYTES>>>(x, Wi0, bi0, bh0, preX);

    // L0(0): h0 buf0 -> buf1
    k_l0<<<dim3(BB / BM, RR / 32), 128, SMEM_BYTES>>>(h0b(0), Wh0, preX, c0, h0b(1));

    // C(u) = L1(u) + L0(u+1), u = 0..8
    for (int u = 0; u < NSTEP - 1; u++) {
        const size_t wo  = (size_t)u * 4 * RR * RR;
        const size_t wn_ = (size_t)(u + 1) * 4 * RR * RR;
        const size_t bo  = (size_t)u * 4 * RR;
        k_step<<<dim3(BB / BM, 64), 128, SMEM_BYTES>>>(
            h0b((u + 1) & 1), h0b(u & 1),
            Wi1 + wo, Wh1 + wo, bi1 + bo, bh1 + bo,
            out + (size_t)u * RR, out + (size_t)(u + 1) * RR,
            Wh0 + wn_, preX + (size_t)(u + 1) * 4 * RR,
            c0, c1);
    }

    // final L1(9)
    {
        const int u = NSTEP - 1;
        const size_t wo = (size_t)u * 4 * RR * RR;
        const size_t bo = (size_t)u * 4 * RR;
        k_l1<<<dim3(BB / BM, RR / 32), 128, SMEM_BYTES>>>(
            h0b((u + 1) & 1), Wi1 + wo,
            out + (size_t)u * RR, Wh1 + wo,
            bi1 + bo, bh1 + bo,
            c1, out + (size_t)(u + 1) * RR);
    }
}

// round 7
// speedup vs baseline: 1.0531x; 1.0531x over previous
#include <cuda_runtime.h>
#include <cstdint>

#define DEVINL __device__ __forceinline__

constexpr int BB = 256;            // batch
constexpr int II = 512;            // input dim
constexpr int RR = 1024;           // hidden dim
constexpr int UU = 11;             // unroll length
constexpr int NSTEP = 10;          // steps that matter (step 10 is dead)
constexpr int OUTLD = UU * RR;     // output row stride
constexpr int PRELD = NSTEP * 4 * RR;  // PreX row stride

constexpr int BM  = 64;            // CTA m-tile
constexpr int BNG = 16;            // n-cols per gate group per CTA (4 groups = 64)
constexpr int KC  = 32;            // k-chunk
constexpr int ALD = KC + 4;        // padded smem row (36) -> conflict-free frags
constexpr int NST = 3;             // pipeline stages

// Scratch (allocation-free rule: __device__ globals)
__device__ __align__(16) float g_preX[(size_t)BB * PRELD];
__device__ __align__(16) float g_h0buf[2][BB * RR];
__device__ __align__(16) float g_c0[BB * RR];
__device__ __align__(16) float g_c1[BB * RR];

struct Smem {
    float As[NST][BM][ALD];
    float Bs[NST][64][ALD];
};
constexpr size_t SMEM_BYTES = sizeof(Smem);   // 3*(64+64)*36*4 = 55,296 B

DEVINL void cp16(float* s, const float* g) {
    uint32_t sa = (uint32_t)__cvta_generic_to_shared(s);
    asm volatile("cp.async.cg.shared.global [%0], [%1], 16;" :: "r"(sa), "l"(g));
}
DEVINL void cp_commit() { asm volatile("cp.async.commit_group;"); }
DEVINL void cp_wait0()  { asm volatile("cp.async.wait_group 0;"); }
DEVINL void cp_wait1()  { asm volatile("cp.async.wait_group 1;"); }

DEVINL uint32_t f2tf(float f) {
    uint32_t u; asm("cvt.rna.tf32.f32 %0, %1;" : "=r"(u) : "f"(f)); return u;
}

DEVINL void mma8(float* d, const uint32_t* a, const uint32_t* b) {
    asm volatile(
        "mma.sync.aligned.m16n8k8.row.col.f32.tf32.tf32.f32 "
        "{%0,%1,%2,%3}, {%4,%5,%6,%7}, {%8,%9}, {%0,%1,%2,%3};"
        : "+f"(d[0]), "+f"(d[1]), "+f"(d[2]), "+f"(d[3])
        : "r"(a[0]), "r"(a[1]), "r"(a[2]), "r"(a[3]), "r"(b[0]), "r"(b[1]));
}

DEVINL float sigm(float x) { return 1.0f / (1.0f + expf(-x)); }

// TN GEMM body, 128 threads = 2x2 warps of 32m x 32n; CTA tile 64m x 64n.
// The 64 output columns are 4 groups of BNG=16 with W-row stride `gstride`
// (the 4 LSTM gates for the same 16 r-columns).
//   EPI 0: precompute -> acc + e0[col] + e1[col] into hout (PreX)
//   EPI 1: layer0 cell -> base = PreX (e0), state c0, write h0_next
//   EPI 2: layer1 cell -> base = bi1+bh1, state c1, write h1
template<int EPI, int NPAIRS>
DEVINL void gemm_body(Smem& sm, int m0, int nbase,
                      const float* __restrict__ A0, int lda0,
                      const float* __restrict__ W0,
                      const float* __restrict__ A1, int lda1,
                      const float* __restrict__ W1,
                      int K, int gstride,
                      const float* __restrict__ e0,
                      const float* __restrict__ e1,
                      float* __restrict__ cst,
                      float* __restrict__ hout, int ldh)
{
    const int tid  = threadIdx.x;
    const int warp = tid >> 5, lane = tid & 31;
    const int wm = warp >> 1, wn = warp & 1;       // 2x2 warps
    const int gid = lane >> 2, tig = lane & 3;

    // loader geometry: 128 threads cover 16 rows x 32 cols per pass
    const int r0 = tid >> 3;                 // 0..15
    const int c0 = (tid & 7) << 2;           // 0,4,...,28

    const float* Ag[NPAIRS];
    const float* Wg[NPAIRS][4];
    #pragma unroll
    for (int p = 0; p < NPAIRS; p++) {
        const float* A   = (p == 0) ? A0 : A1;
        const int    lda = (p == 0) ? lda0 : lda1;
        const float* W   = (p == 0) ? W0 : W1;
        Ag[p] = A + (size_t)(m0 + r0) * lda + c0;
        #pragma unroll
        for (int i = 0; i < 4; i++) {
            const int grow = nbase + i * gstride + r0;   // gate i, row r0
            Wg[p][i] = W + (size_t)grow * K + c0;
        }
    }
    const int ldaP[2] = { lda0, lda1 };

    const int nk = K / KC;
    const int T  = NPAIRS * nk;

    float acc[2][4][4];                       // [mi][gate][reg]
    #pragma unroll
    for (int a = 0; a < 2; a++)
        #pragma unroll
        for (int g = 0; g < 4; g++)
            #pragma unroll
            for (int c = 0; c < 4; c++) acc[a][g][c] = 0.0f;

    // --- prologue: chunks 0,1 ---
    #pragma unroll 1
    for (int ci = 0; ci < 2 && ci < T; ci++) {
        const int buf  = ci % NST;
        const int p    = (NPAIRS == 2 && ci >= nk) ? 1 : 0;
        const int koff = (p ? ci - nk : ci) * KC;
        #pragma unroll
        for (int i = 0; i < 4; i++)
            cp16(&sm.As[buf][r0 + 16 * i][c0], Ag[p] + koff + (size_t)16 * i * ldaP[p]);
        #pragma unroll
        for (int i = 0; i < 4; i++)
            cp16(&sm.Bs[buf][r0 + 16 * i][c0], Wg[p][i] + koff);
        cp_commit();
    }

    #pragma unroll 1
    for (int t = 0; t < T; t++) {
        if (t + 1 < T) cp_wait1(); else cp_wait0();
        __syncthreads();

        const int ci2 = t + 2;
        if (ci2 < T) {
            const int buf  = ci2 % NST;
            const int p    = (NPAIRS == 2 && ci2 >= nk) ? 1 : 0;
            const int koff = (p ? ci2 - nk : ci2) * KC;
            #pragma unroll
            for (int i = 0; i < 4; i++)
                cp16(&sm.As[buf][r0 + 16 * i][c0], Ag[p] + koff + (size_t)16 * i * ldaP[p]);
            #pragma unroll
            for (int i = 0; i < 4; i++)
                cp16(&sm.Bs[buf][r0 + 16 * i][c0], Wg[p][i] + koff);
            cp_commit();
        }

        const int buf = t % NST;
        #pragma unroll
        for (int ks = 0; ks < KC / 8; ks++) {
            const int ko = ks * 8;
            uint32_t ua[2][4];
            #pragma unroll
            for (int mi = 0; mi < 2; mi++) {
                const float* ab = &sm.As[buf][wm * 32 + mi * 16 + gid][ko + tig];
                ua[mi][0] = f2tf(ab[0]);
                ua[mi][1] = f2tf(ab[8 * ALD]);
                ua[mi][2] = f2tf(ab[4]);
                ua[mi][3] = f2tf(ab[8 * ALD + 4]);
            }
            uint32_t ub[4][2];
            #pragma unroll
            for (int g = 0; g < 4; g++) {
                const float* bb = &sm.Bs[buf][g * 16 + wn * 8 + gid][ko + tig];
                ub[g][0] = f2tf(bb[0]);
                ub[g][1] = f2tf(bb[4]);
            }
            #pragma unroll
            for (int mi = 0; mi < 2; mi++)
                #pragma unroll
                for (int g = 0; g < 4; g++)
                    mma8(acc[mi][g], ua[mi], ub[g]);
        }
    }

    // ---- epilogue ----
    #pragma unroll
    for (int mi = 0; mi < 2; mi++) {
        #pragma unroll
        for (int half = 0; half < 2; half++) {
            const int row = wm * 32 + mi * 16 + gid + half * 8;
            const int b = m0 + row;
            #pragma unroll
            for (int cc = 0; cc < 2; cc++) {
                const int reg = half * 2 + cc;
                const int rr = wn * 8 + 2 * tig + cc;      // 0..15 within group
                if constexpr (EPI == 0) {
                    #pragma unroll
                    for (int g = 0; g < 4; g++) {
                        const int col = nbase + g * gstride + rr;
                        hout[(size_t)b * ldh + col] = acc[mi][g][reg] + e0[col] + e1[col];
                    }
                } else {
                    const int r = nbase + rr;
                    float pre[4];
                    #pragma unroll
                    for (int g = 0; g < 4; g++) {
                        float base;
                        if constexpr (EPI == 1)
                            base = e0[(size_t)b * PRELD + g * RR + r];
                        else
                            base = e0[g * RR + r] + e1[g * RR + r];
                        pre[g] = acc[mi][g][reg] + base;
                    }
                    const float cprev = cst[b * RR + r];
                    const float iv = sigm(pre[0]);
                    const float fv = sigm(pre[1]);
                    const float ov = sigm(pre[2]);
                    const float gv = tanhf(pre[3]);
                    const float cnew = fv * cprev + iv * gv;
                    const float hnew = ov * tanhf(cnew);
                    cst[b * RR + r] = cnew;
                    hout[(size_t)b * ldh + r] = hnew;
                }
            }
        }
    }
}

// ---- kernels ----

__global__ __launch_bounds__(128, 4)
void k_pre(const float* __restrict__ x, const float* __restrict__ Wi0,
           const float* __restrict__ bi0, const float* __restrict__ bh0,
           float* __restrict__ preX)
{
    extern __shared__ float smraw[];
    Smem& sm = *reinterpret_cast<Smem*>(smraw);
    // 64 contiguous PreX columns per CTA (gstride=16 makes groups contiguous)
    gemm_body<0, 1>(sm, blockIdx.x * BM, blockIdx.y * 64,
                    x, II, Wi0, nullptr, 0, nullptr,
                    II, 16, bi0, bh0, nullptr, preX, PRELD);
}

__global__ __launch_bounds__(128, 4)
void k_l0(const float* __restrict__ h0cur, const float* __restrict__ Wh0u,
          const float* __restrict__ preXu, float* __restrict__ c0,
          float* __restrict__ h0nxt)
{
    extern __shared__ float smraw[];
    Smem& sm = *reinterpret_cast<Smem*>(smraw);
    gemm_body<1, 1>(sm, blockIdx.x * BM, blockIdx.y * BNG,
                    h0cur, RR, Wh0u, nullptr, 0, nullptr,
                    RR, RR, preXu, nullptr, c0, h0nxt, RR);
}

__global__ __launch_bounds__(128, 4)
void k_l1(const float* __restrict__ h0cur, const float* __restrict__ Wi1u,
          const float* __restrict__ h1in, const float* __restrict__ Wh1u,
          const float* __restrict__ bi1u, const float* __restrict__ bh1u,
          float* __restrict__ c1, float* __restrict__ h1out)
{
    extern __shared__ float smraw[];
    Smem& sm = *reinterpret_cast<Smem*>(smraw);
    gemm_body<2, 2>(sm, blockIdx.x * BM, blockIdx.y * BNG,
                    h0cur, RR, Wi1u, h1in, OUTLD, Wh1u,
                    RR, RR, bi1u, bh1u, c1, h1out, OUTLD);
}

// Combined step: L1(u) [y even, K=2048] and L0(u+1) [y odd, K=1024] are
// independent (both consume h0 from L0(u)). 512 CTAs, ~3.5 CTAs/SM.
__global__ __launch_bounds__(128, 4)
void k_step(const float* __restrict__ h0cur, float* __restrict__ h0nxt,
            const float* __restrict__ Wi1u, const float* __restrict__ Wh1u,
            const float* __restrict__ bi1u, const float* __restrict__ bh1u,
            const float* __restrict__ h1in, float* __restrict__ h1out,
            const float* __restrict__ Wh0n, const float* __restrict__ preXn,
            float* __restrict__ c0, float* __restrict__ c1)
{
    extern __shared__ float smraw[];
    Smem& sm = *reinterpret_cast<Smem*>(smraw);
    const int m0 = blockIdx.x * BM;
    const int y  = blockIdx.y;
    if ((y & 1) == 0) {
        gemm_body<2, 2>(sm, m0, (y >> 1) * BNG,
                        h0cur, RR, Wi1u, h1in, OUTLD, Wh1u,
                        RR, RR, bi1u, bh1u, c1, h1out, OUTLD);
    } else {
        gemm_body<1, 1>(sm, m0, (y >> 1) * BNG,
                        h0cur, RR, Wh0n, nullptr, 0, nullptr,
                        RR, RR, preXn, nullptr, c0, h0nxt, RR);
    }
}

__global__ void init_states(const float* __restrict__ st, float* __restrict__ out) {
    int idx = blockIdx.x * blockDim.x + threadIdx.x;
    if (idx >= BB * RR) return;
    int b = idx >> 10, r = idx & (RR - 1);
    const float* s = st + (size_t)b * (4 * RR);
    g_h0buf[0][idx] = s[r];                        // h0
    g_c0[idx]       = s[RR + r];                   // c0
    out[(size_t)b * OUTLD + r] = s[2 * RR + r];    // h1 -> output col 0 (state)
    g_c1[idx]       = s[3 * RR + r];               // c1
}

extern "C" void kernel_launch(void* const* d_in, const int* in_sizes, int n_in,
                              void* d_out, int out_size)
{
    const float* x   = (const float*)d_in[0];
    const float* ini = (const float*)d_in[1];
    const float* Wi0 = (const float*)d_in[2];
    const float* bi0 = (const float*)d_in[3];
    const float* Wh0 = (const float*)d_in[4];
    const float* bh0 = (const float*)d_in[5];
    const float* Wi1 = (const float*)d_in[6];
    const float* bi1 = (const float*)d_in[7];
    const float* Wh1 = (const float*)d_in[8];
    const float* bh1 = (const float*)d_in[9];
    float* out = (float*)d_out;

    static bool attr_done = false;
    if (!attr_done) {
        cudaFuncSetAttribute(k_pre,  cudaFuncAttributeMaxDynamicSharedMemorySize, (int)SMEM_BYTES);
        cudaFuncSetAttribute(k_l0,   cudaFuncAttributeMaxDynamicSharedMemorySize, (int)SMEM_BYTES);
        cudaFuncSetAttribute(k_l1,   cudaFuncAttributeMaxDynamicSharedMemorySize, (int)SMEM_BYTES);
        cudaFuncSetAttribute(k_step, cudaFuncAttributeMaxDynamicSharedMemorySize, (int)SMEM_BYTES);
        attr_done = true;
    }

    float *preX, *h0buf, *c0, *c1;
    cudaGetSymbolAddress((void**)&preX,  g_preX);
    cudaGetSymbolAddress((void**)&h0buf, g_h0buf);
    cudaGetSymbolAddress((void**)&c0,    g_c0);
    cudaGetSymbolAddress((void**)&c1,    g_c1);

    auto h0b = [&](int i) { return h0buf + (size_t)i * BB * RR; };

    init_states<<<(BB * RR) / 256, 256>>>(ini, out);

    // PreX = x @ Wi0[0:10].T + bi0 + bh0
    k_pre<<<dim3(BB / BM, PRELD / 64), 128, SMEM_BYTES>>>(x, Wi0, bi0, bh0, preX);

    // L0(0): h0 buf0 -> buf1
    k_l0<<<dim3(BB / BM, RR / BNG), 128, SMEM_BYTES>>>(h0b(0), Wh0, preX, c0, h0b(1));

    // C(u) = L1(u) + L0(u+1), u = 0..8
    for (int u = 0; u < NSTEP - 1; u++) {
        const size_t wo  = (size_t)u * 4 * RR * RR;
        const size_t wn_ = (size_t)(u + 1) * 4 * RR * RR;
        const size_t bo  = (size_t)u * 4 * RR;
        k_step<<<dim3(BB / BM, 2 * RR / BNG), 128, SMEM_BYTES>>>(
            h0b((u + 1) & 1), h0b(u & 1),
            Wi1 + wo, Wh1 + wo, bi1 + bo, bh1 + bo,
            out + (size_t)u * RR, out + (size_t)(u + 1) * RR,
            Wh0 + wn_, preX + (size_t)(u + 1) * 4 * RR,
            c0, c1);
    }

    // final L1(9)
    {
        const int u = NSTEP - 1;
        const size_t wo = (size_t)u * 4 * RR * RR;
        const size_t bo = (size_t)u * 4 * RR;
        k_l1<<<dim3(BB / BM, RR / BNG), 128, SMEM_BYTES>>>(
            h0b((u + 1) & 1), Wi1 + wo,
            out + (size_t)u * RR, Wh1 + wo,
            bi1 + bo, bh1 + bo,
            c1, out + (size_t)(u + 1) * RR);
    }
}

// round 9
// speedup vs baseline: 1.5780x; 1.4985x over previous
#include <cuda_runtime.h>
#include <cuda_bf16.h>
#include <cstdint>

#define DEVINL __device__ __forceinline__

constexpr int BB = 256;            // batch
constexpr int II = 512;            // input dim
constexpr int RR = 1024;           // hidden dim
constexpr int UU = 11;             // unroll length
constexpr int NSTEP = 10;          // steps that matter (step 10 is dead)
constexpr int OUTLD = UU * RR;     // output row stride
constexpr int PRELD = NSTEP * 4 * RR;

constexpr int BM  = 128;           // CTA m-tile
constexpr int KC  = 32;            // k-chunk (bf16 elems = 64 bytes)
constexpr int AW  = 20;            // smem row stride in 32-bit words (16 data + 4 pad)
constexpr int NST = 3;             // pipeline stages
// BN = 64 output cols = 4 gates x 16 r-cols

// ---- scratch (__device__ globals; no allocation allowed) ----
__device__ __align__(16) __nv_bfloat16 g_Wi0b[(size_t)NSTEP * 4 * RR * II];
__device__ __align__(16) __nv_bfloat16 g_Wh0b[(size_t)NSTEP * 4 * RR * RR];
__device__ __align__(16) __nv_bfloat16 g_Wi1b[(size_t)NSTEP * 4 * RR * RR];
__device__ __align__(16) __nv_bfloat16 g_Wh1b[(size_t)NSTEP * 4 * RR * RR];
__device__ __align__(16) __nv_bfloat16 g_xb[BB * II];
__device__ __align__(16) __nv_bfloat16 g_h0b[2][BB * RR];
__device__ __align__(16) __nv_bfloat16 g_h1b[2][BB * RR];
__device__ __align__(16) float g_preX[(size_t)BB * PRELD];
__device__ __align__(16) float g_c0[BB * RR];
__device__ __align__(16) float g_c1[BB * RR];

DEVINL void cp16(void* s, const void* g) {
    uint32_t sa = (uint32_t)__cvta_generic_to_shared(s);
    asm volatile("cp.async.cg.shared.global [%0], [%1], 16;" :: "r"(sa), "l"(g));
}
DEVINL void cp_commit() { asm volatile("cp.async.commit_group;"); }
DEVINL void cp_wait0()  { asm volatile("cp.async.wait_group 0;"); }
DEVINL void cp_wait1()  { asm volatile("cp.async.wait_group 1;"); }

DEVINL void mma16(float* d, const uint32_t* a, const uint32_t* b) {
    asm volatile(
        "mma.sync.aligned.m16n8k16.row.col.f32.bf16.bf16.f32 "
        "{%0,%1,%2,%3}, {%4,%5,%6,%7}, {%8,%9}, {%0,%1,%2,%3};"
        : "+f"(d[0]), "+f"(d[1]), "+f"(d[2]), "+f"(d[3])
        : "r"(a[0]), "r"(a[1]), "r"(a[2]), "r"(a[3]), "r"(b[0]), "r"(b[1]));
}

DEVINL float sigm(float x) { return 1.0f / (1.0f + expf(-x)); }

// bf16 TN GEMM body: CTA tile 128m x 64n (4 gates x 16 r), 256 thr = 8 warps
// (4m x 2n of 32m x 32n). W rows for gate g at nbase + g*gstride + r.
// Loader: 256 threads cover 64 rows x 4 16B-segments per cp.async pass ->
//   A (128 rows): 2 passes at row offsets {0, 64}; B (64 rows): 1 pass.
//   EPI 0: precompute -> acc + e0[col] + e1[col] into houtf (PreX, fp32)
//   EPI 1: layer0 cell -> base = PreX, state c0, write h0_next (bf16)
//   EPI 2: layer1 cell -> base = bi1+bh1, state c1, write h1 (fp32 out + bf16)
template<int EPI, int NPAIRS>
DEVINL void gemm_body(uint32_t (&As)[NST][BM][AW], uint32_t (&Bs)[NST][64][AW],
                      int m0, int nbase,
                      const __nv_bfloat16* __restrict__ A0, int lda0,
                      const __nv_bfloat16* __restrict__ W0,
                      const __nv_bfloat16* __restrict__ A1, int lda1,
                      const __nv_bfloat16* __restrict__ W1,
                      int K, int gstride,
                      const float* __restrict__ e0,
                      const float* __restrict__ e1,
                      float* __restrict__ cst,
                      float* __restrict__ houtf, int ldh,
                      __nv_bfloat16* __restrict__ houtb)
{
    const int tid  = threadIdx.x;
    const int warp = tid >> 5, lane = tid & 31;
    const int wm = warp >> 1, wn = warp & 1;       // 4m x 2n warps
    const int gid = lane >> 2, tig = lane & 3;

    const int lr = tid >> 2;                 // 0..63  (loader row)
    const int w  = tid & 3;                  // 16B segment -> bf16 offset 8w, word 4w

    const __nv_bfloat16* Ag[NPAIRS];
    const __nv_bfloat16* Wg[NPAIRS];
    int ldaP[NPAIRS];
    #pragma unroll
    for (int p = 0; p < NPAIRS; p++) {
        const __nv_bfloat16* A = (p == 0) ? A0 : A1;
        const __nv_bfloat16* W = (p == 0) ? W0 : W1;
        ldaP[p] = (p == 0) ? lda0 : lda1;
        Ag[p] = A + (size_t)(m0 + lr) * ldaP[p] + 8 * w;
        const int grow = nbase + (lr >> 4) * gstride + (lr & 15);   // gate, r
        Wg[p] = W + (size_t)grow * K + 8 * w;
    }

    const int nk = K / KC;
    const int T  = NPAIRS * nk;

    float acc[2][4][4];                       // [mi][gate][reg]
    #pragma unroll
    for (int a = 0; a < 2; a++)
        #pragma unroll
        for (int g = 0; g < 4; g++)
            #pragma unroll
            for (int c = 0; c < 4; c++) acc[a][g][c] = 0.0f;

    // --- prologue: chunks 0,1 ---
    #pragma unroll 1
    for (int ci = 0; ci < 2 && ci < T; ci++) {
        const int buf  = ci % NST;
        const int p    = (NPAIRS == 2 && ci >= nk) ? 1 : 0;
        const int koff = (p ? ci - nk : ci) * KC;
        #pragma unroll
        for (int i = 0; i < 2; i++)
            cp16(&As[buf][lr + 64 * i][4 * w],
                 Ag[p] + (size_t)(64 * i) * ldaP[p] + koff);
        cp16(&Bs[buf][lr][4 * w], Wg[p] + koff);
        cp_commit();
    }

    #pragma unroll 1
    for (int t = 0; t < T; t++) {
        if (t + 1 < T) cp_wait1(); else cp_wait0();
        __syncthreads();

        const int ci2 = t + 2;
        if (ci2 < T) {
            const int buf  = ci2 % NST;
            const int p    = (NPAIRS == 2 && ci2 >= nk) ? 1 : 0;
            const int koff = (p ? ci2 - nk : ci2) * KC;
            #pragma unroll
            for (int i = 0; i < 2; i++)
                cp16(&As[buf][lr + 64 * i][4 * w],
                     Ag[p] + (size_t)(64 * i) * ldaP[p] + koff);
            cp16(&Bs[buf][lr][4 * w], Wg[p] + koff);
            cp_commit();
        }

        const int buf = t % NST;
        #pragma unroll
        for (int ks = 0; ks < 2; ks++) {          // two k16 slices per KC=32
            const int kw0 = ks * 8;               // word offset of slice
            uint32_t ua[2][4];
            #pragma unroll
            for (int mi = 0; mi < 2; mi++) {
                const uint32_t* ar = &As[buf][32 * wm + 16 * mi + gid][kw0];
                ua[mi][0] = ar[tig];
                ua[mi][1] = ar[8 * AW + tig];
                ua[mi][2] = ar[tig + 4];
                ua[mi][3] = ar[8 * AW + tig + 4];
            }
            uint32_t ub[4][2];
            #pragma unroll
            for (int g = 0; g < 4; g++) {
                const uint32_t* br = &Bs[buf][g * 16 + 8 * wn + gid][kw0];
                ub[g][0] = br[tig];
                ub[g][1] = br[tig + 4];
            }
            #pragma unroll
            for (int mi = 0; mi < 2; mi++)
                #pragma unroll
                for (int g = 0; g < 4; g++)
                    mma16(acc[mi][g], ua[mi], ub[g]);
        }
    }

    // ---- epilogue ----
    #pragma unroll
    for (int mi = 0; mi < 2; mi++) {
        #pragma unroll
        for (int half = 0; half < 2; half++) {
            const int row = 32 * wm + 16 * mi + gid + 8 * half;
            const int b = m0 + row;
            #pragma unroll
            for (int cc = 0; cc < 2; cc++) {
                const int reg = 2 * half + cc;
                const int rl = 8 * wn + 2 * tig + cc;   // 0..15
                if constexpr (EPI == 0) {
                    #pragma unroll
                    for (int g = 0; g < 4; g++) {
                        const int col = nbase + g * gstride + rl;
                        houtf[(size_t)b * ldh + col] = acc[mi][g][reg] + e0[col] + e1[col];
                    }
                } else {
                    const int r = nbase + rl;
                    float pre[4];
                    #pragma unroll
                    for (int g = 0; g < 4; g++) {
                        float base;
                        if constexpr (EPI == 1)
                            base = e0[(size_t)b * PRELD + g * RR + r];
                        else
                            base = e0[g * RR + r] + e1[g * RR + r];
                        pre[g] = acc[mi][g][reg] + base;
                    }
                    const float cprev = cst[b * RR + r];
                    const float iv = sigm(pre[0]);
                    const float fv = sigm(pre[1]);
                    const float ov = sigm(pre[2]);
                    const float gv = tanhf(pre[3]);
                    const float cnew = fv * cprev + iv * gv;
                    const float hnew = ov * tanhf(cnew);
                    cst[b * RR + r] = cnew;
                    houtb[b * RR + r] = __float2bfloat16_rn(hnew);
                    if constexpr (EPI == 2)
                        houtf[(size_t)b * ldh + r] = hnew;
                }
            }
        }
    }
}

// ---- kernels ----

#define SMEM_DECL \
    __shared__ uint32_t As[NST][BM][AW]; \
    __shared__ uint32_t Bs[NST][64][AW];

__global__ __launch_bounds__(256, 2)
void k_pre(const float* __restrict__ bi0, const float* __restrict__ bh0,
           float* __restrict__ preX)
{
    SMEM_DECL
    const int rg = blockIdx.y * 16;              // global r index 0..10239
    const int u = rg >> 10, rb = rg & 1023;
    const int nbase = u * 4096 + rb;
    gemm_body<0, 1>(As, Bs, blockIdx.x * BM, nbase,
                    g_xb, II, g_Wi0b, nullptr, 0, nullptr,
                    II, RR, bi0, bh0, nullptr, preX, PRELD, nullptr);
}

__global__ __launch_bounds__(256, 2)
void k_l0(const __nv_bfloat16* __restrict__ h0cur, const __nv_bfloat16* __restrict__ Wh0u,
          const float* __restrict__ preXu, float* __restrict__ c0,
          __nv_bfloat16* __restrict__ h0nxt)
{
    SMEM_DECL
    gemm_body<1, 1>(As, Bs, blockIdx.x * BM, blockIdx.y * 16,
                    h0cur, RR, Wh0u, nullptr, 0, nullptr,
                    RR, RR, preXu, nullptr, c0, nullptr, 0, h0nxt);
}

__global__ __launch_bounds__(256, 2)
void k_l1(const __nv_bfloat16* __restrict__ h0cur, const __nv_bfloat16* __restrict__ Wi1u,
          const __nv_bfloat16* __restrict__ h1in, const __nv_bfloat16* __restrict__ Wh1u,
          const float* __restrict__ bi1u, const float* __restrict__ bh1u,
          float* __restrict__ c1, float* __restrict__ h1outf,
          __nv_bfloat16* __restrict__ h1outb)
{
    SMEM_DECL
    gemm_body<2, 2>(As, Bs, blockIdx.x * BM, blockIdx.y * 16,
                    h0cur, RR, Wi1u, h1in, RR, Wh1u,
                    RR, RR, bi1u, bh1u, c1, h1outf, OUTLD, h1outb);
}

// Combined step: y<64 -> L1(u) (K=2048), y>=64 -> L0(u+1) (K=1024); both
// consume h0 from L0(u). Grid 256 CTAs.
__global__ __launch_bounds__(256, 2)
void k_step(const __nv_bfloat16* __restrict__ h0cur, __nv_bfloat16* __restrict__ h0nxt,
            const __nv_bfloat16* __restrict__ Wi1u, const __nv_bfloat16* __restrict__ Wh1u,
            const float* __restrict__ bi1u, const float* __restrict__ bh1u,
            const __nv_bfloat16* __restrict__ h1in, float* __restrict__ h1outf,
            __nv_bfloat16* __restrict__ h1outb,
            const __nv_bfloat16* __restrict__ Wh0n, const float* __restrict__ preXn,
            float* __restrict__ c0, float* __restrict__ c1)
{
    SMEM_DECL
    const int m0 = blockIdx.x * BM;
    const int y  = blockIdx.y;
    if (y < 64) {
        gemm_body<2, 2>(As, Bs, m0, y * 16,
                        h0cur, RR, Wi1u, h1in, RR, Wh1u,
                        RR, RR, bi1u, bh1u, c1, h1outf, OUTLD, h1outb);
    } else {
        gemm_body<1, 1>(As, Bs, m0, (y - 64) * 16,
                        h0cur, RR, Wh0n, nullptr, 0, nullptr,
                        RR, RR, preXn, nullptr, c0, nullptr, 0, h0nxt);
    }
}

// fp32 -> bf16 streaming convert (element counts divisible by 4)
__global__ void k_cvt(const float4* __restrict__ in, uint2* __restrict__ out, int n4) {
    int i = blockIdx.x * blockDim.x + threadIdx.x;
    if (i >= n4) return;
    float4 v = in[i];
    __nv_bfloat162 lo = __floats2bfloat162_rn(v.x, v.y);
    __nv_bfloat162 hi = __floats2bfloat162_rn(v.z, v.w);
    uint2 o;
    o.x = *reinterpret_cast<uint32_t*>(&lo);
    o.y = *reinterpret_cast<uint32_t*>(&hi);
    out[i] = o;
}

__global__ void init_states(const float* __restrict__ st, float* __restrict__ out) {
    int idx = blockIdx.x * blockDim.x + threadIdx.x;
    if (idx >= BB * RR) return;
    int b = idx >> 10, r = idx & (RR - 1);
    const float* s = st + (size_t)b * (4 * RR);
    g_h0b[0][idx] = __float2bfloat16_rn(s[r]);        // h0 (bf16 operand)
    g_c0[idx]     = s[RR + r];                        // c0
    float h1 = s[2 * RR + r];
    g_h1b[0][idx] = __float2bfloat16_rn(h1);          // h1 state (bf16 operand)
    out[(size_t)b * OUTLD + r] = h1;                  // output col 0 (fp32)
    g_c1[idx]     = s[3 * RR + r];                    // c1
}

extern "C" void kernel_launch(void* const* d_in, const int* in_sizes, int n_in,
                              void* d_out, int out_size)
{
    const float* x   = (const float*)d_in[0];
    const float* ini = (const float*)d_in[1];
    const float* Wi0 = (const float*)d_in[2];
    const float* bi0 = (const float*)d_in[3];
    const float* Wh0 = (const float*)d_in[4];
    const float* bh0 = (const float*)d_in[5];
    const float* Wi1 = (const float*)d_in[6];
    const float* bi1 = (const float*)d_in[7];
    const float* Wh1 = (const float*)d_in[8];
    const float* bh1 = (const float*)d_in[9];
    float* out = (float*)d_out;

    float *preX, *c0, *c1;
    __nv_bfloat16 *wi0b, *wh0b, *wi1b, *wh1b, *xb, *h0b, *h1b;
    cudaGetSymbolAddress((void**)&preX, g_preX);
    cudaGetSymbolAddress((void**)&c0,   g_c0);
    cudaGetSymbolAddress((void**)&c1,   g_c1);
    cudaGetSymbolAddress((void**)&wi0b, g_Wi0b);
    cudaGetSymbolAddress((void**)&wh0b, g_Wh0b);
    cudaGetSymbolAddress((void**)&wi1b, g_Wi1b);
    cudaGetSymbolAddress((void**)&wh1b, g_Wh1b);
    cudaGetSymbolAddress((void**)&xb,   g_xb);
    cudaGetSymbolAddress((void**)&h0b,  g_h0b);
    cudaGetSymbolAddress((void**)&h1b,  g_h1b);

    auto h0p = [&](int i) { return h0b + (size_t)i * BB * RR; };
    auto h1p = [&](int i) { return h1b + (size_t)i * BB * RR; };

    // ---- bf16 conversion of weights + x (graph nodes; all independent) ----
    auto cvt = [&](const float* src, __nv_bfloat16* dst, size_t n) {
        int n4 = (int)(n / 4);
        k_cvt<<<(n4 + 255) / 256, 256>>>((const float4*)src, (uint2*)dst, n4);
    };
    cvt(x,   xb,   (size_t)BB * II);
    cvt(Wi0, wi0b, (size_t)NSTEP * 4 * RR * II);    // u < 10 rows only
    cvt(Wh0, wh0b, (size_t)NSTEP * 4 * RR * RR);
    cvt(Wi1, wi1b, (size_t)NSTEP * 4 * RR * RR);
    cvt(Wh1, wh1b, (size_t)NSTEP * 4 * RR * RR);

    init_states<<<(BB * RR) / 256, 256>>>(ini, out);

    // PreX = x @ Wi0[0:10].T + bi0 + bh0
    k_pre<<<dim3(BB / BM, PRELD / 64), 256>>>(bi0, bh0, preX);

    // L0(0): h0 buf0 -> buf1
    k_l0<<<dim3(BB / BM, RR / 16), 256>>>(h0p(0), wh0b, preX, c0, h0p(1));

    // C(u) = L1(u) + L0(u+1), u = 0..8
    for (int u = 0; u < NSTEP - 1; u++) {
        const size_t wo  = (size_t)u * 4 * RR * RR;
        const size_t wn_ = (size_t)(u + 1) * 4 * RR * RR;
        const size_t bo  = (size_t)u * 4 * RR;
        k_step<<<dim3(BB / BM, 128), 256>>>(
            h0p((u + 1) & 1), h0p(u & 1),
            wi1b + wo, wh1b + wo, bi1 + bo, bh1 + bo,
            h1p(u & 1), out + (size_t)(u + 1) * RR, h1p((u + 1) & 1),
            wh0b + wn_, preX + (size_t)(u + 1) * 4 * RR,
            c0, c1);
    }

    // final L1(9)
    {
        const int u = NSTEP - 1;
        const size_t wo = (size_t)u * 4 * RR * RR;
        const size_t bo = (size_t)u * 4 * RR;
        k_l1<<<dim3(BB / BM, RR / 16), 256>>>(
            h0p((u + 1) & 1), wi1b + wo,
            h1p(u & 1), wh1b + wo,
            bi1 + bo, bh1 + bo,
            c1, out + (size_t)(u + 1) * RR, h1p((u + 1) & 1));
    }
}

// round 10
// speedup vs baseline: 1.6423x; 1.0407x over previous
#include <cuda_runtime.h>
#include <cuda_bf16.h>
#include <cstdint>

#define DEVINL __device__ __forceinline__

constexpr int BB = 256;            // batch
constexpr int II = 512;            // input dim
constexpr int RR = 1024;           // hidden dim
constexpr int UU = 11;             // unroll length
constexpr int NSTEP = 10;          // steps that matter (step 10 is dead)
constexpr int OUTLD = UU * RR;     // output row stride
constexpr int PRELD = NSTEP * 4 * RR;

constexpr int BM  = 128;           // CTA m-tile
constexpr int KC  = 32;            // k-chunk (bf16 elems = 64 bytes)
constexpr int AW  = 20;            // smem row stride in 32-bit words (16 data + 4 pad)
constexpr int NST = 3;             // pipeline stages
// BN = 64 output cols = 4 gates x 16 r-cols

// ---- scratch (__device__ globals; no allocation allowed) ----
__device__ __align__(16) __nv_bfloat16 g_Wi0b[(size_t)NSTEP * 4 * RR * II];
__device__ __align__(16) __nv_bfloat16 g_Wh0b[(size_t)NSTEP * 4 * RR * RR];
__device__ __align__(16) __nv_bfloat16 g_Wi1b[(size_t)NSTEP * 4 * RR * RR];
__device__ __align__(16) __nv_bfloat16 g_Wh1b[(size_t)NSTEP * 4 * RR * RR];
__device__ __align__(16) __nv_bfloat16 g_xb[BB * II];
__device__ __align__(16) __nv_bfloat16 g_h0b[2][BB * RR];
__device__ __align__(16) __nv_bfloat16 g_h1b[2][BB * RR];
__device__ __align__(16) float g_preX[(size_t)BB * PRELD];
__device__ __align__(16) float g_c0[BB * RR];
__device__ __align__(16) float g_c1[BB * RR];

DEVINL void cp16(void* s, const void* g) {
    uint32_t sa = (uint32_t)__cvta_generic_to_shared(s);
    asm volatile("cp.async.cg.shared.global [%0], [%1], 16;" :: "r"(sa), "l"(g));
}
DEVINL void cp_commit() { asm volatile("cp.async.commit_group;"); }
DEVINL void cp_wait0()  { asm volatile("cp.async.wait_group 0;"); }
DEVINL void cp_wait1()  { asm volatile("cp.async.wait_group 1;"); }

DEVINL void ldsm4(uint32_t& r0, uint32_t& r1, uint32_t& r2, uint32_t& r3,
                  const void* p) {
    uint32_t a = (uint32_t)__cvta_generic_to_shared(p);
    asm volatile("ldmatrix.sync.aligned.m8n8.x4.shared.b16 {%0,%1,%2,%3}, [%4];"
                 : "=r"(r0), "=r"(r1), "=r"(r2), "=r"(r3) : "r"(a));
}

DEVINL void mma16(float* d, const uint32_t* a, const uint32_t* b) {
    asm volatile(
        "mma.sync.aligned.m16n8k16.row.col.f32.bf16.bf16.f32 "
        "{%0,%1,%2,%3}, {%4,%5,%6,%7}, {%8,%9}, {%0,%1,%2,%3};"
        : "+f"(d[0]), "+f"(d[1]), "+f"(d[2]), "+f"(d[3])
        : "r"(a[0]), "r"(a[1]), "r"(a[2]), "r"(a[3]), "r"(b[0]), "r"(b[1]));
}

DEVINL float sigm(float x) { return 1.0f / (1.0f + expf(-x)); }

// bf16 TN GEMM body: CTA tile 128m x 64n (4 gates x 16 r), 256 thr = 8 warps
// (4m x 2n of 32m x 32n). W rows for gate g at nbase + g*gstride + r.
// Loader: 256 threads cover 64 rows x 4 16B-segments per cp.async pass ->
//   A (128 rows): 2 passes at row offsets {0, 64}; B (64 rows): 1 pass.
// Fragment loads via ldmatrix.x4:
//   A (per mi): matrices (m0-7,k0-7)(m8-15,k0-7)(m0-7,k8-15)(m8-15,k8-15)
//     -> lane addr: row = 32*wm + 16*mi + (lane&15), word = kw0 + 4*(lane>>4)
//   B (per gate-pair gp): matrices (g,b0)(g,b1)(g+1,b0)(g+1,b1)
//     -> lane addr: row = (2gp + ((lane>>4)&1))*16 + 8*wn + (lane&7),
//        word = kw0 + 4*((lane>>3)&1)
template<int EPI, int NPAIRS>
DEVINL void gemm_body(uint32_t (&As)[NST][BM][AW], uint32_t (&Bs)[NST][64][AW],
                      int m0, int nbase,
                      const __nv_bfloat16* __restrict__ A0, int lda0,
                      const __nv_bfloat16* __restrict__ W0,
                      const __nv_bfloat16* __restrict__ A1, int lda1,
                      const __nv_bfloat16* __restrict__ W1,
                      int K, int gstride,
                      const float* __restrict__ e0,
                      const float* __restrict__ e1,
                      float* __restrict__ cst,
                      float* __restrict__ houtf, int ldh,
                      __nv_bfloat16* __restrict__ houtb)
{
    const int tid  = threadIdx.x;
    const int warp = tid >> 5, lane = tid & 31;
    const int wm = warp >> 1, wn = warp & 1;       // 4m x 2n warps
    const int gid = lane >> 2, tig = lane & 3;

    const int lr = tid >> 2;                 // 0..63  (loader row)
    const int w  = tid & 3;                  // 16B segment -> bf16 offset 8w, word 4w

    // ldmatrix lane-derived coordinates (constant across the k-loop)
    const int a_row = 32 * wm + (lane & 15);          // + 16*mi
    const int a_wof = (lane >> 4) << 2;               // + kw0
    const int b_row = ((lane >> 4) & 1) * 16 + 8 * wn + (lane & 7);  // + 32*gp
    const int b_wof = ((lane >> 3) & 1) << 2;         // + kw0

    const __nv_bfloat16* Ag[NPAIRS];
    const __nv_bfloat16* Wg[NPAIRS];
    int ldaP[NPAIRS];
    #pragma unroll
    for (int p = 0; p < NPAIRS; p++) {
        const __nv_bfloat16* A = (p == 0) ? A0 : A1;
        const __nv_bfloat16* W = (p == 0) ? W0 : W1;
        ldaP[p] = (p == 0) ? lda0 : lda1;
        Ag[p] = A + (size_t)(m0 + lr) * ldaP[p] + 8 * w;
        const int grow = nbase + (lr >> 4) * gstride + (lr & 15);   // gate, r
        Wg[p] = W + (size_t)grow * K + 8 * w;
    }

    const int nk = K / KC;
    const int T  = NPAIRS * nk;

    float acc[2][4][4];                       // [mi][gate][reg]
    #pragma unroll
    for (int a = 0; a < 2; a++)
        #pragma unroll
        for (int g = 0; g < 4; g++)
            #pragma unroll
            for (int c = 0; c < 4; c++) acc[a][g][c] = 0.0f;

    // --- prologue: chunks 0,1 ---
    #pragma unroll 1
    for (int ci = 0; ci < 2 && ci < T; ci++) {
        const int buf  = ci % NST;
        const int p    = (NPAIRS == 2 && ci >= nk) ? 1 : 0;
        const int koff = (p ? ci - nk : ci) * KC;
        #pragma unroll
        for (int i = 0; i < 2; i++)
            cp16(&As[buf][lr + 64 * i][4 * w],
                 Ag[p] + (size_t)(64 * i) * ldaP[p] + koff);
        cp16(&Bs[buf][lr][4 * w], Wg[p] + koff);
        cp_commit();
    }

    #pragma unroll 1
    for (int t = 0; t < T; t++) {
        if (t + 1 < T) cp_wait1(); else cp_wait0();
        __syncthreads();

        const int ci2 = t + 2;
        if (ci2 < T) {
            const int buf  = ci2 % NST;
            const int p    = (NPAIRS == 2 && ci2 >= nk) ? 1 : 0;
            const int koff = (p ? ci2 - nk : ci2) * KC;
            #pragma unroll
            for (int i = 0; i < 2; i++)
                cp16(&As[buf][lr + 64 * i][4 * w],
                     Ag[p] + (size_t)(64 * i) * ldaP[p] + koff);
            cp16(&Bs[buf][lr][4 * w], Wg[p] + koff);
            cp_commit();
        }

        const int buf = t % NST;
        #pragma unroll
        for (int ks = 0; ks < 2; ks++) {          // two k16 slices per KC=32
            const int kw0 = ks * 8;               // word offset of slice
            uint32_t ua[2][4];
            #pragma unroll
            for (int mi = 0; mi < 2; mi++)
                ldsm4(ua[mi][0], ua[mi][1], ua[mi][2], ua[mi][3],
                      &As[buf][a_row + 16 * mi][kw0 + a_wof]);
            uint32_t ub[4][2];
            #pragma unroll
            for (int gp = 0; gp < 2; gp++)
                ldsm4(ub[2 * gp][0], ub[2 * gp][1],
                      ub[2 * gp + 1][0], ub[2 * gp + 1][1],
                      &Bs[buf][b_row + 32 * gp][kw0 + b_wof]);
            #pragma unroll
            for (int mi = 0; mi < 2; mi++)
                #pragma unroll
                for (int g = 0; g < 4; g++)
                    mma16(acc[mi][g], ua[mi], ub[g]);
        }
    }

    // ---- epilogue ----
    #pragma unroll
    for (int mi = 0; mi < 2; mi++) {
        #pragma unroll
        for (int half = 0; half < 2; half++) {
            const int row = 32 * wm + 16 * mi + gid + 8 * half;
            const int b = m0 + row;
            #pragma unroll
            for (int cc = 0; cc < 2; cc++) {
                const int reg = 2 * half + cc;
                const int rl = 8 * wn + 2 * tig + cc;   // 0..15
                if constexpr (EPI == 0) {
                    #pragma unroll
                    for (int g = 0; g < 4; g++) {
                        const int col = nbase + g * gstride + rl;
                        houtf[(size_t)b * ldh + col] = acc[mi][g][reg] + e0[col] + e1[col];
                    }
                } else {
                    const int r = nbase + rl;
                    float pre[4];
                    #pragma unroll
                    for (int g = 0; g < 4; g++) {
                        float base;
                        if constexpr (EPI == 1)
                            base = e0[(size_t)b * PRELD + g * RR + r];
                        else
                            base = e0[g * RR + r] + e1[g * RR + r];
                        pre[g] = acc[mi][g][reg] + base;
                    }
                    const float cprev = cst[b * RR + r];
                    const float iv = sigm(pre[0]);
                    const float fv = sigm(pre[1]);
                    const float ov = sigm(pre[2]);
                    const float gv = tanhf(pre[3]);
                    const float cnew = fv * cprev + iv * gv;
                    const float hnew = ov * tanhf(cnew);
                    cst[b * RR + r] = cnew;
                    houtb[b * RR + r] = __float2bfloat16_rn(hnew);
                    if constexpr (EPI == 2)
                        houtf[(size_t)b * ldh + r] = hnew;
                }
            }
        }
    }
}

// ---- kernels ----

#define SMEM_DECL \
    __shared__ uint32_t As[NST][BM][AW]; \
    __shared__ uint32_t Bs[NST][64][AW];

__global__ __launch_bounds__(256, 2)
void k_pre(const float* __restrict__ bi0, const float* __restrict__ bh0,
           float* __restrict__ preX)
{
    SMEM_DECL
    const int rg = blockIdx.y * 16;              // global r index 0..10239
    const int u = rg >> 10, rb = rg & 1023;
    const int nbase = u * 4096 + rb;
    gemm_body<0, 1>(As, Bs, blockIdx.x * BM, nbase,
                    g_xb, II, g_Wi0b, nullptr, 0, nullptr,
                    II, RR, bi0, bh0, nullptr, preX, PRELD, nullptr);
}

__global__ __launch_bounds__(256, 2)
void k_l0(const __nv_bfloat16* __restrict__ h0cur, const __nv_bfloat16* __restrict__ Wh0u,
          const float* __restrict__ preXu, float* __restrict__ c0,
          __nv_bfloat16* __restrict__ h0nxt)
{
    SMEM_DECL
    gemm_body<1, 1>(As, Bs, blockIdx.x * BM, blockIdx.y * 16,
                    h0cur, RR, Wh0u, nullptr, 0, nullptr,
                    RR, RR, preXu, nullptr, c0, nullptr, 0, h0nxt);
}

__global__ __launch_bounds__(256, 2)
void k_l1(const __nv_bfloat16* __restrict__ h0cur, const __nv_bfloat16* __restrict__ Wi1u,
          const __nv_bfloat16* __restrict__ h1in, const __nv_bfloat16* __restrict__ Wh1u,
          const float* __restrict__ bi1u, const float* __restrict__ bh1u,
          float* __restrict__ c1, float* __restrict__ h1outf,
          __nv_bfloat16* __restrict__ h1outb)
{
    SMEM_DECL
    gemm_body<2, 2>(As, Bs, blockIdx.x * BM, blockIdx.y * 16,
                    h0cur, RR, Wi1u, h1in, RR, Wh1u,
                    RR, RR, bi1u, bh1u, c1, h1outf, OUTLD, h1outb);
}

// Combined step: y<64 -> L1(u) (K=2048), y>=64 -> L0(u+1) (K=1024); both
// consume h0 from L0(u). Grid 256 CTAs.
__global__ __launch_bounds__(256, 2)
void k_step(const __nv_bfloat16* __restrict__ h0cur, __nv_bfloat16* __restrict__ h0nxt,
            const __nv_bfloat16* __restrict__ Wi1u, const __nv_bfloat16* __restrict__ Wh1u,
            const float* __restrict__ bi1u, const float* __restrict__ bh1u,
            const __nv_bfloat16* __restrict__ h1in, float* __restrict__ h1outf,
            __nv_bfloat16* __restrict__ h1outb,
            const __nv_bfloat16* __restrict__ Wh0n, const float* __restrict__ preXn,
            float* __restrict__ c0, float* __restrict__ c1)
{
    SMEM_DECL
    const int m0 = blockIdx.x * BM;
    const int y  = blockIdx.y;
    if (y < 64) {
        gemm_body<2, 2>(As, Bs, m0, y * 16,
                        h0cur, RR, Wi1u, h1in, RR, Wh1u,
                        RR, RR, bi1u, bh1u, c1, h1outf, OUTLD, h1outb);
    } else {
        gemm_body<1, 1>(As, Bs, m0, (y - 64) * 16,
                        h0cur, RR, Wh0n, nullptr, 0, nullptr,
                        RR, RR, preXn, nullptr, c0, nullptr, 0, h0nxt);
    }
}

// fp32 -> bf16 streaming convert (element counts divisible by 4)
__global__ void k_cvt(const float4* __restrict__ in, uint2* __restrict__ out, int n4) {
    int i = blockIdx.x * blockDim.x + threadIdx.x;
    if (i >= n4) return;
    float4 v = in[i];
    __nv_bfloat162 lo = __floats2bfloat162_rn(v.x, v.y);
    __nv_bfloat162 hi = __floats2bfloat162_rn(v.z, v.w);
    uint2 o;
    o.x = *reinterpret_cast<uint32_t*>(&lo);
    o.y = *reinterpret_cast<uint32_t*>(&hi);
    out[i] = o;
}

__global__ void init_states(const float* __restrict__ st, float* __restrict__ out) {
    int idx = blockIdx.x * blockDim.x + threadIdx.x;
    if (idx >= BB * RR) return;
    int b = idx >> 10, r = idx & (RR - 1);
    const float* s = st + (size_t)b * (4 * RR);
    g_h0b[0][idx] = __float2bfloat16_rn(s[r]);        // h0 (bf16 operand)
    g_c0[idx]     = s[RR + r];                        // c0
    float h1 = s[2 * RR + r];
    g_h1b[0][idx] = __float2bfloat16_rn(h1);          // h1 state (bf16 operand)
    out[(size_t)b * OUTLD + r] = h1;                  // output col 0 (fp32)
    g_c1[idx]     = s[3 * RR + r];                    // c1
}

extern "C" void kernel_launch(void* const* d_in, const int* in_sizes, int n_in,
                              void* d_out, int out_size)
{
    const float* x   = (const float*)d_in[0];
    const float* ini = (const float*)d_in[1];
    const float* Wi0 = (const float*)d_in[2];
    const float* bi0 = (const float*)d_in[3];
    const float* Wh0 = (const float*)d_in[4];
    const float* bh0 = (const float*)d_in[5];
    const float* Wi1 = (const float*)d_in[6];
    const float* bi1 = (const float*)d_in[7];
    const float* Wh1 = (const float*)d_in[8];
    const float* bh1 = (const float*)d_in[9];
    float* out = (float*)d_out;

    float *preX, *c0, *c1;
    __nv_bfloat16 *wi0b, *wh0b, *wi1b, *wh1b, *xb, *h0b, *h1b;
    cudaGetSymbolAddress((void**)&preX, g_preX);
    cudaGetSymbolAddress((void**)&c0,   g_c0);
    cudaGetSymbolAddress((void**)&c1,   g_c1);
    cudaGetSymbolAddress((void**)&wi0b, g_Wi0b);
    cudaGetSymbolAddress((void**)&wh0b, g_Wh0b);
    cudaGetSymbolAddress((void**)&wi1b, g_Wi1b);
    cudaGetSymbolAddress((void**)&wh1b, g_Wh1b);
    cudaGetSymbolAddress((void**)&xb,   g_xb);
    cudaGetSymbolAddress((void**)&h0b,  g_h0b);
    cudaGetSymbolAddress((void**)&h1b,  g_h1b);

    auto h0p = [&](int i) { return h0b + (size_t)i * BB * RR; };
    auto h1p = [&](int i) { return h1b + (size_t)i * BB * RR; };

    // ---- bf16 conversion of weights + x ----
    auto cvt = [&](const float* src, __nv_bfloat16* dst, size_t n) {
        int n4 = (int)(n / 4);
        k_cvt<<<(n4 + 255) / 256, 256>>>((const float4*)src, (uint2*)dst, n4);
    };
    cvt(x,   xb,   (size_t)BB * II);
    cvt(Wi0, wi0b, (size_t)NSTEP * 4 * RR * II);    // u < 10 rows only
    cvt(Wh0, wh0b, (size_t)NSTEP * 4 * RR * RR);
    cvt(Wi1, wi1b, (size_t)NSTEP * 4 * RR * RR);
    cvt(Wh1, wh1b, (size_t)NSTEP * 4 * RR * RR);

    init_states<<<(BB * RR) / 256, 256>>>(ini, out);

    // PreX = x @ Wi0[0:10].T + bi0 + bh0
    k_pre<<<dim3(BB / BM, PRELD / 64), 256>>>(bi0, bh0, preX);

    // L0(0): h0 buf0 -> buf1
    k_l0<<<dim3(BB / BM, RR / 16), 256>>>(h0p(0), wh0b, preX, c0, h0p(1));

    // C(u) = L1(u) + L0(u+1), u = 0..8
    for (int u = 0; u < NSTEP - 1; u++) {
        const size_t wo  = (size_t)u * 4 * RR * RR;
        const size_t wn_ = (size_t)(u + 1) * 4 * RR * RR;
        const size_t bo  = (size_t)u * 4 * RR;
        k_step<<<dim3(BB / BM, 128), 256>>>(
            h0p((u + 1) & 1), h0p(u & 1),
            wi1b + wo, wh1b + wo, bi1 + bo, bh1 + bo,
            h1p(u & 1), out + (size_t)(u + 1) * RR, h1p((u + 1) & 1),
            wh0b + wn_, preX + (size_t)(u + 1) * 4 * RR,
            c0, c1);
    }

    // final L1(9)
    {
        const int u = NSTEP - 1;
        const size_t wo = (size_t)u * 4 * RR * RR;
        const size_t bo = (size_t)u * 4 * RR;
        k_l1<<<dim3(BB / BM, RR / 16), 256>>>(
            h0p((u + 1) & 1), wi1b + wo,
            h1p(u & 1), wh1b + wo,
            bi1 + bo, bh1 + bo,
            c1, out + (size_t)(u + 1) * RR, h1p((u + 1) & 1));
    }
}